// round 10
// baseline (speedup 1.0000x reference)
#include <cuda_runtime.h>
#include <cuda_fp16.h>
#include <cstdint>

#define BB 4
#define LL 2048
#define DD 1024
#define HH 16
#define NROWS (BB*LL)
#define D3 (3*DD)

// ---------------- persistent scratch (allocation-free) ----------------------
__device__ __half   g_xh16[(size_t)NROWS*DD];
__device__ uint8_t  g_xh8 [(size_t)NROWS*DD], g_xl8[(size_t)NROWS*DD];
__device__ __half   g_w1h16[(size_t)DD*D3];                 // W1^T [3072][1024]
__device__ uint8_t  g_w1h8[(size_t)DD*D3], g_w1l8[(size_t)DD*D3];
__device__ __half   g_w2h16[(size_t)DD*DD];                 // W2^T
__device__ uint8_t  g_w2h8[(size_t)DD*DD], g_w2l8[(size_t)DD*DD];
__device__ __half   g_qh[(size_t)NROWS*D3], g_ql[(size_t)NROWS*D3];
__device__ __half   g_ch16[(size_t)NROWS*DD];
__device__ uint8_t  g_ch8[(size_t)NROWS*DD], g_cl8[(size_t)NROWS*DD];
__device__ uint32_t g_pm[(size_t)BB*LL*(LL/32)];

// ---------------- helpers ---------------------------------------------------
__device__ __forceinline__ float fexp2(float x) {
    float y; asm("ex2.approx.ftz.f32 %0, %1;" : "=f"(y) : "f"(x)); return y;
}
__device__ __forceinline__ void cp16(uint32_t smem_dst, const void* gmem_src) {
    asm volatile("cp.async.cg.shared.global [%0], [%1], 16;\n" :: "r"(smem_dst), "l"(gmem_src));
}
__device__ __forceinline__ void cp_async16(void* smem_dst, const void* gmem_src) {
    cp16((uint32_t)__cvta_generic_to_shared(smem_dst), gmem_src);
}
#define CP_COMMIT() asm volatile("cp.async.commit_group;\n" ::: "memory")
#define CP_WAIT1()  asm volatile("cp.async.wait_group 1;\n" ::: "memory")
#define CP_WAIT0()  asm volatile("cp.async.wait_group 0;\n" ::: "memory")
__device__ __forceinline__ uint32_t su32(const void* p) {
    return (uint32_t)__cvta_generic_to_shared(p);
}
__device__ __forceinline__ uint32_t h2bits(__half2 h) {
    uint32_t r; memcpy(&r, &h, 4); return r;
}
__device__ __forceinline__ void split_pair_h(float x, float y, uint32_t& hp, uint32_t& lp) {
    __half2 h = __floats2half2_rn(x, y);
    hp = h2bits(h);
    float2 f = __half22float2(h);
    lp = h2bits(__floats2half2_rn(x - f.x, y - f.y));
}
__device__ __forceinline__ uint16_t pack_e4(float x, float y) {
    uint16_t r;
    asm("cvt.rn.satfinite.e4m3x2.f32 %0, %1, %2;" : "=h"(r) : "f"(y), "f"(x));
    return r;
}
__device__ __forceinline__ void mma_f16(float c[4], const uint32_t a[4],
                                        uint32_t b0, uint32_t b1) {
    asm volatile(
        "mma.sync.aligned.m16n8k16.row.col.f32.f16.f16.f32 "
        "{%0,%1,%2,%3}, {%4,%5,%6,%7}, {%8,%9}, {%0,%1,%2,%3};\n"
        : "+f"(c[0]), "+f"(c[1]), "+f"(c[2]), "+f"(c[3])
        : "r"(a[0]), "r"(a[1]), "r"(a[2]), "r"(a[3]), "r"(b0), "r"(b1));
}
__device__ __forceinline__ void mma_e4(float c[4], const uint32_t a[4],
                                       uint32_t b0, uint32_t b1) {
    asm volatile(
        "mma.sync.aligned.m16n8k32.row.col.f32.e4m3.e4m3.f32 "
        "{%0,%1,%2,%3}, {%4,%5,%6,%7}, {%8,%9}, {%0,%1,%2,%3};\n"
        : "+f"(c[0]), "+f"(c[1]), "+f"(c[2]), "+f"(c[3])
        : "r"(a[0]), "r"(a[1]), "r"(a[2]), "r"(a[3]), "r"(b0), "r"(b1));
}
__device__ __forceinline__ void ldsm_x4(uint32_t r[4], uint32_t addr) {
    asm volatile("ldmatrix.sync.aligned.m8n8.x4.shared.b16 {%0,%1,%2,%3}, [%4];"
        : "=r"(r[0]), "=r"(r[1]), "=r"(r[2]), "=r"(r[3]) : "r"(addr));
}
__device__ __forceinline__ void ldsm_x4_t(uint32_t r[4], uint32_t addr) {
    asm volatile("ldmatrix.sync.aligned.m8n8.x4.trans.shared.b16 {%0,%1,%2,%3}, [%4];"
        : "=r"(r[0]), "=r"(r[1]), "=r"(r[2]), "=r"(r[3]) : "r"(addr));
}

// ---------------- pre-pass kernels ------------------------------------------
__global__ void split_x3(const float* __restrict__ src, __half* __restrict__ h16,
                         uint8_t* __restrict__ h8, uint8_t* __restrict__ l8, int n4) {
    int i = blockIdx.x * 256 + threadIdx.x;
    if (i >= n4) return;
    float4 v = ((const float4*)src)[i];
    __half2 ha = __floats2half2_rn(v.x, v.y);
    __half2 hb = __floats2half2_rn(v.z, v.w);
    ((uint2*)h16)[i] = make_uint2(h2bits(ha), h2bits(hb));
    ((uint32_t*)h8)[i] = (uint32_t)pack_e4(v.x, v.y) | ((uint32_t)pack_e4(v.z, v.w) << 16);
    float2 fa = __half22float2(ha), fb = __half22float2(hb);
    ((uint32_t*)l8)[i] =
          (uint32_t)pack_e4((v.x - fa.x)*2048.f, (v.y - fa.y)*2048.f)
        | ((uint32_t)pack_e4((v.z - fb.x)*2048.f, (v.w - fb.y)*2048.f) << 16);
}

// W [K][N] fp32 -> transposed [N][K]: h16, h8 = fp8(w*32), l8 = fp8((w-h16)*65536)
__global__ void transpose_split3(const float* __restrict__ src,
                                 __half* __restrict__ th, uint8_t* __restrict__ t8,
                                 uint8_t* __restrict__ tl8, int K, int N) {
    __shared__ float tile[32][33];
    const int x0 = blockIdx.x * 32, y0 = blockIdx.y * 32;
    const int tx = threadIdx.x, ty = threadIdx.y;
    #pragma unroll
    for (int j = 0; j < 4; j++)
        tile[ty + 8*j][tx] = src[(size_t)(y0 + ty + 8*j) * N + x0 + tx];
    __syncthreads();
    #pragma unroll
    for (int j = 0; j < 4; j++) {
        const int n = x0 + ty + 8*j, k = y0 + tx;
        float v = tile[tx][ty + 8*j];
        __half h = __float2half_rn(v);
        th[(size_t)n * K + k] = h;
        t8[(size_t)n * K + k]  = (uint8_t)(pack_e4(v * 32.f, 0.f) & 0xFF);
        tl8[(size_t)n * K + k] = (uint8_t)(pack_e4((v - __half2float(h)) * 65536.f, 0.f) & 0xFF);
    }
}

__global__ void pack_mask_kernel(const int* __restrict__ m, uint32_t* __restrict__ pm,
                                 int nwords) {
    int i = blockIdx.x * 256 + threadIdx.x;
    if (i >= nwords) return;
    const int4* src = (const int4*)m + (size_t)i * 8;
    uint32_t w = 0;
    #pragma unroll
    for (int j = 0; j < 8; j++) {
        int4 v = src[j];
        w |= (v.x != 0 ? 1u : 0u) << (4*j);
        w |= (v.y != 0 ? 1u : 0u) << (4*j + 1);
        w |= (v.z != 0 ? 1u : 0u) << (4*j + 2);
        w |= (v.w != 0 ? 1u : 0u) << (4*j + 3);
    }
    pm[i] = w;
}

// ---------------------------------------------------------------------------
// fp8-assisted GEMM: C = A @ Bt^T + bias.
// acc1 += a16*b16 (f16 k16); acc2 += a8h*b8l + a8l*b8h (e4m3 k32); C = acc1 + acc2*2^-16.
// 512 thr (16 warps 4x4, warp tile 32x32), 128x128x32 tiles, 3-stage cp.async.
// Stage 45056B: A16[128][40h] B16[128][40h] | A8h A8l B8h B8l [128][48B each].
// ---------------------------------------------------------------------------
#define G_STAGES 3
#define G_STAGE  45056
#define B16_OFF  10240
#define F8_OFF   20480
#define G_SMEM   (G_STAGES * G_STAGE)   // 135168
#define CROSS_SCALE (1.0f/65536.0f)

template<bool SPLIT_OUT>
__global__ __launch_bounds__(512, 1)
void gemm_f8(const __half* __restrict__ Ah16, const uint8_t* __restrict__ Ah8,
             const uint8_t* __restrict__ Al8,
             const __half* __restrict__ Bh16, const uint8_t* __restrict__ Bh8,
             const uint8_t* __restrict__ Bl8,
             const float* __restrict__ bias, float* __restrict__ Cf,
             __half* __restrict__ Ch, __half* __restrict__ Cl,
             int M, int N, int K)
{
    extern __shared__ __align__(128) char smem[];
    const uint32_t smem_b = su32(smem);
    const int tid  = threadIdx.x;
    const int warp = tid >> 5, lane = tid & 31;
    const int g = lane >> 2, t = lane & 3;
    const int wr = (warp >> 2) * 32;
    const int wc = (warp & 3) * 32;
    const int row0 = blockIdx.y * 128;
    const int col0 = blockIdx.x * 128;
    const int ntiles = K / 32;

    const int r16 = tid >> 2;            // 0..127
    const int s16 = (tid & 3) * 16;      // byte seg of 64B row

    const uint8_t* f8src[2];
    uint32_t f8dst[2];
    #pragma unroll
    for (int p = 0; p < 2; p++) {
        int q = tid + 512*p;
        int pl = q >> 8, idx = q & 255;
        int r8 = idx >> 1, sg = (idx & 1) * 16;
        const uint8_t* bp = (pl == 0) ? Ah8 : (pl == 1) ? Al8 : (pl == 2) ? Bh8 : Bl8;
        int base = (pl < 2) ? row0 : col0;
        f8src[p] = bp + (size_t)(base + r8) * K + sg;
        f8dst[p] = F8_OFF + (uint32_t)pl * 6144u + (uint32_t)r8 * 48u + (uint32_t)sg;
    }

    auto load_tile = [&](int kt) {
        const uint32_t sb = smem_b + (uint32_t)(kt % G_STAGES) * G_STAGE;
        cp16(sb + r16*80 + s16,           Ah16 + (size_t)(row0 + r16) * K + kt*32 + s16/2);
        cp16(sb + B16_OFF + r16*80 + s16, Bh16 + (size_t)(col0 + r16) * K + kt*32 + s16/2);
        #pragma unroll
        for (int p = 0; p < 2; p++) cp16(sb + f8dst[p], f8src[p] + kt*32);
        CP_COMMIT();
    };

    float acc1[2][4][4], acc2[2][4][4];
    #pragma unroll
    for (int mi = 0; mi < 2; mi++)
        #pragma unroll
        for (int ni = 0; ni < 4; ni++)
            #pragma unroll
            for (int j = 0; j < 4; j++) { acc1[mi][ni][j] = 0.f; acc2[mi][ni][j] = 0.f; }

    load_tile(0);
    load_tile(1);

    const int a_row = lane & 15;
    const int a_hc  = (lane >> 4) << 3;      // f16 elem offset
    const int a_bc  = (lane >> 4) << 4;      // byte offset (fp8)
    const int b_row = ((lane & 16) ? 8 : 0) + (lane & 7);
    const int b_hc  = (lane & 8) ? 8 : 0;
    const int b_bc  = (lane & 8) ? 16 : 0;

    for (int kt = 0; kt < ntiles; kt++) {
        if (kt < ntiles - 1) CP_WAIT1(); else CP_WAIT0();
        __syncthreads();
        if (kt + 2 < ntiles) load_tile(kt + 2);

        const uint32_t sb = smem_b + (uint32_t)(kt % G_STAGES) * G_STAGE;

        #pragma unroll
        for (int ks = 0; ks < 2; ks++) {
            uint32_t a16[2][4];
            #pragma unroll
            for (int mi = 0; mi < 2; mi++)
                ldsm_x4(a16[mi], sb + (wr + mi*16 + a_row)*80 + (ks*16 + a_hc)*2);
            #pragma unroll
            for (int njp = 0; njp < 2; njp++) {
                uint32_t kb[4];
                ldsm_x4(kb, sb + B16_OFF + (wc + njp*16 + b_row)*80 + (ks*16 + b_hc)*2);
                #pragma unroll
                for (int mi = 0; mi < 2; mi++) {
                    mma_f16(acc1[mi][2*njp],   a16[mi], kb[0], kb[1]);
                    mma_f16(acc1[mi][2*njp+1], a16[mi], kb[2], kb[3]);
                }
            }
        }
        uint32_t a8h[2][4], a8l[2][4];
        #pragma unroll
        for (int mi = 0; mi < 2; mi++) {
            ldsm_x4(a8h[mi], sb + F8_OFF          + (wr + mi*16 + a_row)*48 + a_bc);
            ldsm_x4(a8l[mi], sb + F8_OFF + 6144u  + (wr + mi*16 + a_row)*48 + a_bc);
        }
        #pragma unroll
        for (int njp = 0; njp < 2; njp++) {
            uint32_t b8h[4], b8l[4];
            ldsm_x4(b8h, sb + F8_OFF + 12288u + (wc + njp*16 + b_row)*48 + b_bc);
            ldsm_x4(b8l, sb + F8_OFF + 18432u + (wc + njp*16 + b_row)*48 + b_bc);
            #pragma unroll
            for (int mi = 0; mi < 2; mi++) {
                mma_e4(acc2[mi][2*njp],   a8h[mi], b8l[0], b8l[1]);
                mma_e4(acc2[mi][2*njp],   a8l[mi], b8h[0], b8h[1]);
                mma_e4(acc2[mi][2*njp+1], a8h[mi], b8l[2], b8l[3]);
                mma_e4(acc2[mi][2*njp+1], a8l[mi], b8h[2], b8h[3]);
            }
        }
    }

    #pragma unroll
    for (int mi = 0; mi < 2; mi++) {
        const int r = row0 + wr + mi*16 + g;
        #pragma unroll
        for (int ni = 0; ni < 4; ni++) {
            const int c = col0 + wc + ni*8 + 2*t;
            float2 bb = *(const float2*)&bias[c];
            float v0 = acc1[mi][ni][0] + acc2[mi][ni][0]*CROSS_SCALE + bb.x;
            float v1 = acc1[mi][ni][1] + acc2[mi][ni][1]*CROSS_SCALE + bb.y;
            float v2 = acc1[mi][ni][2] + acc2[mi][ni][2]*CROSS_SCALE + bb.x;
            float v3 = acc1[mi][ni][3] + acc2[mi][ni][3]*CROSS_SCALE + bb.y;
            if (SPLIT_OUT) {
                uint32_t hp, lp;
                split_pair_h(v0, v1, hp, lp);
                *(uint32_t*)&Ch[(size_t)r * N + c] = hp;
                *(uint32_t*)&Cl[(size_t)r * N + c] = lp;
                split_pair_h(v2, v3, hp, lp);
                *(uint32_t*)&Ch[(size_t)(r + 8) * N + c] = hp;
                *(uint32_t*)&Cl[(size_t)(r + 8) * N + c] = lp;
            } else {
                *(float2*)&Cf[(size_t)r * N + c]       = make_float2(v0, v1);
                *(float2*)&Cf[(size_t)(r + 8) * N + c] = make_float2(v2, v3);
            }
        }
    }
}

// ---------------------------------------------------------------------------
// Fused masked flash attention, fp16 3-pass, BM=128, 256 thr / 8 warps.
// Epilogue emits ctx h16 + h8 + l8 planes for the fp8-assisted GEMM2.
// Masked score -> 0.0 (in max + denominator), attn weight zeroed for PV.
// ---------------------------------------------------------------------------
#define KV_PAD 72
#define ASTAGES 3
#define ASTAGE_BYTES 36864
#define QST_OFF (ASTAGES * ASTAGE_BYTES)                 // 110592
#define ATTN_SMEM_BYTES (QST_OFF + 2*128*KV_PAD*2)       // 147456

__global__ __launch_bounds__(256, 1)
void attn_f16(const __half* __restrict__ qh, const __half* __restrict__ ql,
              const uint32_t* __restrict__ pm,
              __half* __restrict__ cth, uint8_t* __restrict__ ct8,
              uint8_t* __restrict__ ctl8)
{
    extern __shared__ __align__(16) char smem_raw[];
    __half* QstH = (__half*)(smem_raw + QST_OFF);
    __half* QstL = (__half*)(smem_raw + QST_OFF + 128*KV_PAD*2);

    const int tid  = threadIdx.x;
    const int warp = tid >> 5, lane = tid & 31;
    const int g = lane >> 2, t = lane & 3;
    const int b  = blockIdx.y >> 4;
    const int h  = blockIdx.y & 15;
    const int q0 = blockIdx.x * 128;

    const size_t rowbase = (size_t)b * LL;
    const uint32_t* pmb = pm + (size_t)b * LL * (LL/32);

    #pragma unroll
    for (int p = 0; p < 4; p++) {
        int idx = p * 256 + tid;            // 128 rows x 8 segs
        int r   = idx >> 3;
        int ch  = (idx & 7) * 8;
        size_t src = (rowbase + q0 + r) * (size_t)D3 + h*64 + ch;
        cp_async16(&QstH[r*KV_PAD + ch], qh + src);
        cp_async16(&QstL[r*KV_PAD + ch], ql + src);
    }
    CP_COMMIT();

    auto load_kv = [&](int tile, int slot) {
        char* sb = smem_raw + slot * ASTAGE_BYTES;
        __half* KsH = (__half*)sb;
        __half* KsL = (__half*)(sb + 9216);
        __half* VsH = (__half*)(sb + 18432);
        __half* VsL = (__half*)(sb + 27648);
        const int k0 = tile * 64;
        #pragma unroll
        for (int p = 0; p < 2; p++) {
            int idx = p * 256 + tid;        // 64 rows x 8 segs
            int r   = idx >> 3;
            int ch  = (idx & 7) * 8;
            size_t base = (rowbase + k0 + r) * (size_t)D3 + h*64 + ch;
            cp_async16(&KsH[r*KV_PAD + ch], qh + base + 1024);
            cp_async16(&KsL[r*KV_PAD + ch], ql + base + 1024);
            cp_async16(&VsH[r*KV_PAD + ch], qh + base + 2048);
            cp_async16(&VsL[r*KV_PAD + ch], ql + base + 2048);
        }
    };

    load_kv(0, 0); CP_COMMIT();
    load_kv(1, 1); CP_COMMIT();

    float oc[8][4];
    #pragma unroll
    for (int ni = 0; ni < 8; ni++)
        #pragma unroll
        for (int j = 0; j < 4; j++) oc[ni][j] = 0.f;
    float mi0 = -1e30f, mi1 = -1e30f, li0 = 0.f, li1 = 0.f;

    const float cs = 0.18033688011112042f;  // log2(e)/sqrt(64)
    const int r0g = q0 + warp*16 + g;
    const int NT  = LL / 64;

    const int k_key = ((lane & 16) ? 8 : 0) + (lane & 7);
    const int k_dim = (lane & 8) ? 8 : 0;
    const int v_row = lane;
    const int q_row = warp*16 + (lane & 15);
    const int q_col = (lane >> 4) << 3;

    for (int tt = 0; tt < NT; tt++) {
        const int k0 = tt * 64;
        if (tt < NT - 1) CP_WAIT1(); else CP_WAIT0();
        __syncthreads();

        if (tt + 2 < NT) { load_kv(tt + 2, (tt + 2) % ASTAGES); CP_COMMIT(); }

        char* sb = smem_raw + (tt % ASTAGES) * ASTAGE_BYTES;
        const __half* KsH = (const __half*)sb;
        const __half* KsL = (const __half*)(sb + 9216);
        const __half* VsH = (const __half*)(sb + 18432);
        const __half* VsL = (const __half*)(sb + 27648);

        float sc[8][4];
        #pragma unroll
        for (int ni = 0; ni < 8; ni++)
            #pragma unroll
            for (int j = 0; j < 4; j++) sc[ni][j] = 0.f;

        #pragma unroll
        for (int kb = 0; kb < 4; kb++) {
            uint32_t aqH[4], aqL[4];
            ldsm_x4(aqH, su32(QstH + q_row*KV_PAD + kb*16 + q_col));
            ldsm_x4(aqL, su32(QstL + q_row*KV_PAD + kb*16 + q_col));
            #pragma unroll
            for (int njp = 0; njp < 4; njp++) {
                uint32_t kH[4], kL[4];
                ldsm_x4(kH, su32(KsH + (njp*16 + k_key)*KV_PAD + kb*16 + k_dim));
                ldsm_x4(kL, su32(KsL + (njp*16 + k_key)*KV_PAD + kb*16 + k_dim));
                mma_f16(sc[2*njp],   aqH, kH[0], kH[1]);
                mma_f16(sc[2*njp],   aqH, kL[0], kL[1]);
                mma_f16(sc[2*njp],   aqL, kH[0], kH[1]);
                mma_f16(sc[2*njp+1], aqH, kH[2], kH[3]);
                mma_f16(sc[2*njp+1], aqH, kL[2], kL[3]);
                mma_f16(sc[2*njp+1], aqL, kH[2], kH[3]);
            }
        }

        const uint32_t* pr0 = pmb + (size_t)r0g * 64 + (k0 >> 5);
        const uint32_t* pr1 = pmb + (size_t)(r0g + 8) * 64 + (k0 >> 5);
        uint64_t m0 = (uint64_t)pr0[0] | ((uint64_t)pr0[1] << 32);
        uint64_t m1 = (uint64_t)pr1[0] | ((uint64_t)pr1[1] << 32);

        float tm0 = -1e30f, tm1 = -1e30f;
        uint32_t keep[8];
        #pragma unroll
        for (int ni = 0; ni < 8; ni++) {
            const int bit = ni*8 + 2*t;
            uint32_t p0 = (uint32_t)(m0 >> bit) & 3u;
            uint32_t p1 = (uint32_t)(m1 >> bit) & 3u;
            keep[ni] = p0 | (p1 << 2);
            sc[ni][0] = (p0 & 1) ? sc[ni][0]*cs : 0.f;
            sc[ni][1] = (p0 & 2) ? sc[ni][1]*cs : 0.f;
            sc[ni][2] = (p1 & 1) ? sc[ni][2]*cs : 0.f;
            sc[ni][3] = (p1 & 2) ? sc[ni][3]*cs : 0.f;
            tm0 = fmaxf(tm0, fmaxf(sc[ni][0], sc[ni][1]));
            tm1 = fmaxf(tm1, fmaxf(sc[ni][2], sc[ni][3]));
        }
        tm0 = fmaxf(tm0, __shfl_xor_sync(0xffffffffu, tm0, 1));
        tm0 = fmaxf(tm0, __shfl_xor_sync(0xffffffffu, tm0, 2));
        tm1 = fmaxf(tm1, __shfl_xor_sync(0xffffffffu, tm1, 1));
        tm1 = fmaxf(tm1, __shfl_xor_sync(0xffffffffu, tm1, 2));

        const float mn0 = fmaxf(mi0, tm0);
        const float mn1 = fmaxf(mi1, tm1);
        const float s0  = fexp2(mi0 - mn0);
        const float s1  = fexp2(mi1 - mn1);
        mi0 = mn0; mi1 = mn1;

        float sum0 = 0.f, sum1 = 0.f;
        #pragma unroll
        for (int ni = 0; ni < 8; ni++) {
            float e0 = fexp2(sc[ni][0] - mn0);
            float e1 = fexp2(sc[ni][1] - mn0);
            float e2 = fexp2(sc[ni][2] - mn1);
            float e3 = fexp2(sc[ni][3] - mn1);
            sum0 += e0 + e1;
            sum1 += e2 + e3;
            sc[ni][0] = (keep[ni] & 1) ? e0 : 0.f;
            sc[ni][1] = (keep[ni] & 2) ? e1 : 0.f;
            sc[ni][2] = (keep[ni] & 4) ? e2 : 0.f;
            sc[ni][3] = (keep[ni] & 8) ? e3 : 0.f;
        }
        sum0 += __shfl_xor_sync(0xffffffffu, sum0, 1);
        sum0 += __shfl_xor_sync(0xffffffffu, sum0, 2);
        sum1 += __shfl_xor_sync(0xffffffffu, sum1, 1);
        sum1 += __shfl_xor_sync(0xffffffffu, sum1, 2);
        li0 = li0 * s0 + sum0;
        li1 = li1 * s1 + sum1;

        #pragma unroll
        for (int ni = 0; ni < 8; ni++) {
            oc[ni][0] *= s0; oc[ni][1] *= s0;
            oc[ni][2] *= s1; oc[ni][3] *= s1;
        }

        #pragma unroll
        for (int kb2 = 0; kb2 < 2; kb2++) {
            uint32_t apH[2][4], apL[2][4];
            #pragma unroll
            for (int kk = 0; kk < 2; kk++) {
                const int kbi = kb2*2 + kk;
                split_pair_h(sc[2*kbi][0],   sc[2*kbi][1],   apH[kk][0], apL[kk][0]);
                split_pair_h(sc[2*kbi][2],   sc[2*kbi][3],   apH[kk][1], apL[kk][1]);
                split_pair_h(sc[2*kbi+1][0], sc[2*kbi+1][1], apH[kk][2], apL[kk][2]);
                split_pair_h(sc[2*kbi+1][2], sc[2*kbi+1][3], apH[kk][3], apL[kk][3]);
            }
            #pragma unroll
            for (int nj = 0; nj < 8; nj++) {
                uint32_t vH[4], vL[4];
                ldsm_x4_t(vH, su32(VsH + (kb2*32 + v_row)*KV_PAD + nj*8));
                ldsm_x4_t(vL, su32(VsL + (kb2*32 + v_row)*KV_PAD + nj*8));
                mma_f16(oc[nj], apH[0], vH[0], vH[1]);
                mma_f16(oc[nj], apH[0], vL[0], vL[1]);
                mma_f16(oc[nj], apL[0], vH[0], vH[1]);
                mma_f16(oc[nj], apH[1], vH[2], vH[3]);
                mma_f16(oc[nj], apH[1], vL[2], vL[3]);
                mma_f16(oc[nj], apL[1], vH[2], vH[3]);
            }
        }
    }

    // epilogue: ctx h16 + h8 + l8 planes
    const float inv0 = 1.0f / li0;
    const float inv1 = 1.0f / li1;
    #pragma unroll
    for (int ni = 0; ni < 8; ni++) {
        const int c = h*64 + ni*8 + 2*t;
        float v0 = oc[ni][0]*inv0, v1 = oc[ni][1]*inv0;
        float v2 = oc[ni][2]*inv1, v3 = oc[ni][3]*inv1;
        size_t o0 = (rowbase + r0g) * DD + c;
        size_t o1 = (rowbase + r0g + 8) * DD + c;
        __half2 ha = __floats2half2_rn(v0, v1);
        __half2 hb = __floats2half2_rn(v2, v3);
        *(uint32_t*)&cth[o0] = h2bits(ha);
        *(uint32_t*)&cth[o1] = h2bits(hb);
        *(uint16_t*)&ct8[o0] = pack_e4(v0, v1);
        *(uint16_t*)&ct8[o1] = pack_e4(v2, v3);
        float2 fa = __half22float2(ha), fb = __half22float2(hb);
        *(uint16_t*)&ctl8[o0] = pack_e4((v0 - fa.x)*2048.f, (v1 - fa.y)*2048.f);
        *(uint16_t*)&ctl8[o1] = pack_e4((v2 - fb.x)*2048.f, (v3 - fb.y)*2048.f);
    }
}

// ---------------------------------------------------------------------------
extern "C" void kernel_launch(void* const* d_in, const int* in_sizes, int n_in,
                              void* d_out, int out_size)
{
    const float* inputs = (const float*)d_in[0];
    const int*   mask   = (const int*)  d_in[1];
    const float* W1     = (const float*)d_in[2];
    const float* b1     = (const float*)d_in[3];
    const float* W2     = (const float*)d_in[4];
    const float* b2     = (const float*)d_in[5];
    float* out = (float*)d_out;

    __half *xh16, *w1h16, *w2h16, *qh, *ql, *ch16;
    uint8_t *xh8, *xl8, *w1h8, *w1l8, *w2h8, *w2l8, *ch8, *cl8;
    uint32_t* pmm;
    cudaGetSymbolAddress((void**)&xh16,  g_xh16);
    cudaGetSymbolAddress((void**)&xh8,   g_xh8);
    cudaGetSymbolAddress((void**)&xl8,   g_xl8);
    cudaGetSymbolAddress((void**)&w1h16, g_w1h16);
    cudaGetSymbolAddress((void**)&w1h8,  g_w1h8);
    cudaGetSymbolAddress((void**)&w1l8,  g_w1l8);
    cudaGetSymbolAddress((void**)&w2h16, g_w2h16);
    cudaGetSymbolAddress((void**)&w2h8,  g_w2h8);
    cudaGetSymbolAddress((void**)&w2l8,  g_w2l8);
    cudaGetSymbolAddress((void**)&qh,    g_qh);
    cudaGetSymbolAddress((void**)&ql,    g_ql);
    cudaGetSymbolAddress((void**)&ch16,  g_ch16);
    cudaGetSymbolAddress((void**)&ch8,   g_ch8);
    cudaGetSymbolAddress((void**)&cl8,   g_cl8);
    cudaGetSymbolAddress((void**)&pmm,   g_pm);

    cudaFuncSetAttribute(gemm_f8<true>,
                         cudaFuncAttributeMaxDynamicSharedMemorySize, G_SMEM);
    cudaFuncSetAttribute(gemm_f8<false>,
                         cudaFuncAttributeMaxDynamicSharedMemorySize, G_SMEM);
    cudaFuncSetAttribute(attn_f16,
                         cudaFuncAttributeMaxDynamicSharedMemorySize, ATTN_SMEM_BYTES);

    // 0) pre-passes
    {
        int nx = NROWS*DD/4;
        split_x3<<<(nx+255)/256, 256>>>(inputs, xh16, xh8, xl8, nx);
        dim3 tb(32, 8);
        transpose_split3<<<dim3(D3/32, DD/32), tb>>>(W1, w1h16, w1h8, w1l8, DD, D3);
        transpose_split3<<<dim3(DD/32, DD/32), tb>>>(W2, w2h16, w2h8, w2l8, DD, DD);
        int nw = BB*LL*(LL/32);
        pack_mask_kernel<<<(nw+255)/256, 256>>>(mask, pmm, nw);
    }
    // 1) QKV projection -> qkv fp16 hi/lo planes
    {
        dim3 grid(D3/128, NROWS/128);
        gemm_f8<true><<<grid, 512, G_SMEM>>>(
            xh16, xh8, xl8, w1h16, w1h8, w1l8, b1, nullptr, qh, ql, NROWS, D3, DD);
    }
    // 2) fused masked attention -> ctx h16/h8/l8 planes
    {
        dim3 grid(LL/128, BB*HH);
        attn_f16<<<grid, 256, ATTN_SMEM_BYTES>>>(qh, ql, pmm, ch16, ch8, cl8);
    }
    // 3) output projection -> fp32 out
    {
        dim3 grid(DD/128, NROWS/128);
        gemm_f8<false><<<grid, 512, G_SMEM>>>(
            ch16, ch8, cl8, w2h16, w2h8, w2l8, b2, out, nullptr, nullptr, NROWS, DD, DD);
    }
}

// round 11
// speedup vs baseline: 1.3030x; 1.3030x over previous
#include <cuda_runtime.h>
#include <cuda_fp16.h>
#include <cstdint>

#define BB 4
#define LL 2048
#define DD 1024
#define HH 16
#define NROWS (BB*LL)
#define D3 (3*DD)

// ---------------- persistent scratch (allocation-free) ----------------------
__device__ __half   g_xh[(size_t)NROWS*DD],  g_xl[(size_t)NROWS*DD];
__device__ __half   g_w1h[(size_t)DD*D3],    g_w1l[(size_t)DD*D3];   // [K][N]
__device__ __half   g_w2h[(size_t)DD*DD],    g_w2l[(size_t)DD*DD];   // [K][N]
__device__ __half   g_qh[(size_t)NROWS*D3],  g_ql[(size_t)NROWS*D3];
__device__ __half   g_ch[(size_t)NROWS*DD],  g_cl[(size_t)NROWS*DD];
__device__ uint32_t g_pm[(size_t)BB*LL*(LL/32)];   // packed mask bits

// ---------------- helpers ---------------------------------------------------
__device__ __forceinline__ float fexp2(float x) {
    float y; asm("ex2.approx.ftz.f32 %0, %1;" : "=f"(y) : "f"(x)); return y;
}
__device__ __forceinline__ void cp16(uint32_t smem_dst, const void* gmem_src) {
    asm volatile("cp.async.cg.shared.global [%0], [%1], 16;\n" :: "r"(smem_dst), "l"(gmem_src));
}
__device__ __forceinline__ void cp_async16(void* smem_dst, const void* gmem_src) {
    cp16((uint32_t)__cvta_generic_to_shared(smem_dst), gmem_src);
}
#define CP_COMMIT() asm volatile("cp.async.commit_group;\n" ::: "memory")
#define CP_WAIT2()  asm volatile("cp.async.wait_group 2;\n" ::: "memory")
#define CP_WAIT1()  asm volatile("cp.async.wait_group 1;\n" ::: "memory")
#define CP_WAIT0()  asm volatile("cp.async.wait_group 0;\n" ::: "memory")
__device__ __forceinline__ uint32_t su32(const void* p) {
    return (uint32_t)__cvta_generic_to_shared(p);
}
__device__ __forceinline__ uint32_t h2bits(__half2 h) {
    uint32_t r; memcpy(&r, &h, 4); return r;
}
// fp16 split: (x,y) -> hi pack + lo pack (x in low half)
__device__ __forceinline__ void split_pair_h(float x, float y, uint32_t& hp, uint32_t& lp) {
    __half2 h = __floats2half2_rn(x, y);
    hp = h2bits(h);
    float2 f = __half22float2(h);
    lp = h2bits(__floats2half2_rn(x - f.x, y - f.y));
}
__device__ __forceinline__ void mma_f16(float c[4], const uint32_t a[4],
                                        uint32_t b0, uint32_t b1) {
    asm volatile(
        "mma.sync.aligned.m16n8k16.row.col.f32.f16.f16.f32 "
        "{%0,%1,%2,%3}, {%4,%5,%6,%7}, {%8,%9}, {%0,%1,%2,%3};\n"
        : "+f"(c[0]), "+f"(c[1]), "+f"(c[2]), "+f"(c[3])
        : "r"(a[0]), "r"(a[1]), "r"(a[2]), "r"(a[3]), "r"(b0), "r"(b1));
}
__device__ __forceinline__ void ldsm_x4(uint32_t r[4], uint32_t addr) {
    asm volatile("ldmatrix.sync.aligned.m8n8.x4.shared.b16 {%0,%1,%2,%3}, [%4];"
        : "=r"(r[0]), "=r"(r[1]), "=r"(r[2]), "=r"(r[3]) : "r"(addr));
}
__device__ __forceinline__ void ldsm_x4_t(uint32_t r[4], uint32_t addr) {
    asm volatile("ldmatrix.sync.aligned.m8n8.x4.trans.shared.b16 {%0,%1,%2,%3}, [%4];"
        : "=r"(r[0]), "=r"(r[1]), "=r"(r[2]), "=r"(r[3]) : "r"(addr));
}

// ---------------- pre-pass kernels ------------------------------------------
__global__ void split_kernel(const float* __restrict__ src,
                             __half* __restrict__ h, __half* __restrict__ l, int n4) {
    int i = blockIdx.x * 256 + threadIdx.x;
    if (i >= n4) return;
    float4 v = ((const float4*)src)[i];
    uint32_t h0, l0, h1, l1;
    split_pair_h(v.x, v.y, h0, l0);
    split_pair_h(v.z, v.w, h1, l1);
    ((uint2*)h)[i] = make_uint2(h0, h1);
    ((uint2*)l)[i] = make_uint2(l0, l1);
}

__global__ void pack_mask_kernel(const int* __restrict__ m, uint32_t* __restrict__ pm,
                                 int nwords) {
    int i = blockIdx.x * 256 + threadIdx.x;
    if (i >= nwords) return;
    const int4* src = (const int4*)m + (size_t)i * 8;
    uint32_t w = 0;
    #pragma unroll
    for (int j = 0; j < 8; j++) {
        int4 v = src[j];
        w |= (v.x != 0 ? 1u : 0u) << (4*j);
        w |= (v.y != 0 ? 1u : 0u) << (4*j + 1);
        w |= (v.z != 0 ? 1u : 0u) << (4*j + 2);
        w |= (v.w != 0 ? 1u : 0u) << (4*j + 3);
    }
    pm[i] = w;
}

// ---------------------------------------------------------------------------
// fp16x3 GEMM (structure = round-7 proven kernel, types fp16).
// 512 threads (16 warps 4x4, warp tile 32x32), 128x128x32 tiles, 4-stage pipe.
// Stage (37888 B): AsH[128][40] | AsL | BsH[32][136] | BsL   (fp16 elems)
// ---------------------------------------------------------------------------
#define GSTAGES 4
#define GSTAGE_BYTES 37888
#define GEMM_SMEM_BYTES (GSTAGES * GSTAGE_BYTES)   // 151552

template<bool SPLIT_OUT>
__global__ __launch_bounds__(512, 1)
void gemm_f16x3(const __half* __restrict__ Ah, const __half* __restrict__ Al,
                const __half* __restrict__ Wh, const __half* __restrict__ Wl,
                const float* __restrict__ bias, float* __restrict__ Cf,
                __half* __restrict__ Ch, __half* __restrict__ Cl,
                int M, int N, int K)
{
    extern __shared__ __align__(16) char smem_raw[];

    const int tid  = threadIdx.x;
    const int warp = tid >> 5, lane = tid & 31;
    const int g = lane >> 2, t = lane & 3;
    const int wr = (warp >> 2) * 32;
    const int wc = (warp & 3) * 32;
    const int row0 = blockIdx.y * 128;
    const int col0 = blockIdx.x * 128;
    const int ntiles = K / 32;

    const int a_m = tid >> 2;              // 0..127
    const int a_c = (tid & 3) * 8;         // fp16 offset
    const int b_k = tid >> 4;              // 0..31
    const int b_c = (tid & 15) * 8;

    auto load_tile = [&](int kt, int slot) {
        char* sb = smem_raw + slot * GSTAGE_BYTES;
        __half* AsH = (__half*)sb;
        __half* AsL = (__half*)(sb + 10240);
        __half* BsH = (__half*)(sb + 20480);
        __half* BsL = (__half*)(sb + 29184);
        cp_async16(&AsH[a_m*40 + a_c], Ah + (size_t)(row0 + a_m) * K + kt*32 + a_c);
        cp_async16(&AsL[a_m*40 + a_c], Al + (size_t)(row0 + a_m) * K + kt*32 + a_c);
        cp_async16(&BsH[b_k*136 + b_c], Wh + (size_t)(kt*32 + b_k) * N + col0 + b_c);
        cp_async16(&BsL[b_k*136 + b_c], Wl + (size_t)(kt*32 + b_k) * N + col0 + b_c);
    };

    float acc[2][4][4];
    #pragma unroll
    for (int mi = 0; mi < 2; mi++)
        #pragma unroll
        for (int ni = 0; ni < 4; ni++)
            #pragma unroll
            for (int j = 0; j < 4; j++) acc[mi][ni][j] = 0.0f;

    #pragma unroll
    for (int s = 0; s < GSTAGES-1; s++) { load_tile(s, s); CP_COMMIT(); }

    const int a_row = (lane & 15);
    const int a_col = (lane >> 4) << 3;
    const int b_row = (lane & 15);
    const int b_col = (lane >> 4) << 3;

    for (int kt = 0; kt < ntiles; kt++) {
        if (kt < ntiles - 2)      CP_WAIT2();
        else if (kt == ntiles-2)  CP_WAIT1();
        else                      CP_WAIT0();
        __syncthreads();

        if (kt + GSTAGES - 1 < ntiles) {
            load_tile(kt + GSTAGES - 1, (kt + GSTAGES - 1) % GSTAGES);
            CP_COMMIT();
        }

        char* sb = smem_raw + (kt % GSTAGES) * GSTAGE_BYTES;
        const __half* AsH = (const __half*)sb;
        const __half* AsL = (const __half*)(sb + 10240);
        const __half* BsH = (const __half*)(sb + 20480);
        const __half* BsL = (const __half*)(sb + 29184);

        #pragma unroll
        for (int ks = 0; ks < 2; ks++) {
            const int k0 = ks * 16;
            uint32_t aH[2][4], aL[2][4];
            #pragma unroll
            for (int mi = 0; mi < 2; mi++) {
                ldsm_x4(aH[mi], su32(AsH + (wr + mi*16 + a_row)*40 + k0 + a_col));
                ldsm_x4(aL[mi], su32(AsL + (wr + mi*16 + a_row)*40 + k0 + a_col));
            }
            #pragma unroll
            for (int njp = 0; njp < 2; njp++) {
                const int n0 = wc + njp * 16;
                uint32_t bH[4], bL[4];
                ldsm_x4_t(bH, su32(BsH + (k0 + b_row)*136 + n0 + b_col));
                ldsm_x4_t(bL, su32(BsL + (k0 + b_row)*136 + n0 + b_col));
                #pragma unroll
                for (int mi = 0; mi < 2; mi++) {
                    mma_f16(acc[mi][2*njp],   aH[mi], bH[0], bH[1]);
                    mma_f16(acc[mi][2*njp],   aH[mi], bL[0], bL[1]);
                    mma_f16(acc[mi][2*njp],   aL[mi], bH[0], bH[1]);
                    mma_f16(acc[mi][2*njp+1], aH[mi], bH[2], bH[3]);
                    mma_f16(acc[mi][2*njp+1], aH[mi], bL[2], bL[3]);
                    mma_f16(acc[mi][2*njp+1], aL[mi], bH[2], bH[3]);
                }
            }
        }
    }

    #pragma unroll
    for (int mi = 0; mi < 2; mi++) {
        const int r = row0 + wr + mi*16 + g;
        #pragma unroll
        for (int ni = 0; ni < 4; ni++) {
            const int c = col0 + wc + ni*8 + 2*t;
            float2 bb = *(const float2*)&bias[c];
            float v0 = acc[mi][ni][0] + bb.x, v1 = acc[mi][ni][1] + bb.y;
            float v2 = acc[mi][ni][2] + bb.x, v3 = acc[mi][ni][3] + bb.y;
            if (SPLIT_OUT) {
                uint32_t hp, lp;
                split_pair_h(v0, v1, hp, lp);
                *(uint32_t*)&Ch[(size_t)r * N + c] = hp;
                *(uint32_t*)&Cl[(size_t)r * N + c] = lp;
                split_pair_h(v2, v3, hp, lp);
                *(uint32_t*)&Ch[(size_t)(r + 8) * N + c] = hp;
                *(uint32_t*)&Cl[(size_t)(r + 8) * N + c] = lp;
            } else {
                *(float2*)&Cf[(size_t)r * N + c]       = make_float2(v0, v1);
                *(float2*)&Cf[(size_t)(r + 8) * N + c] = make_float2(v2, v3);
            }
        }
    }
}

// ---------------------------------------------------------------------------
// Fused masked flash attention, fp16 2-PASS, BM=128, 256 thr / 8 warps.
// S = qH @ (kH + kL)^T  (2 mma per njp-half; Q lo plane unused)
// O += pH @ (vH + vL)   (2 mma per nj; P not split)
// Error budget: each dropped lo*hi term ~2^-12 RMS-relative.
// Smem: KV stages [0,110592) | QstH [110592, 129024).
// Masked score -> 0.0 (in max + denominator), attn weight zeroed for PV.
// ---------------------------------------------------------------------------
#define KV_PAD 72
#define ASTAGES 3
#define ASTAGE_BYTES 36864
#define QST_OFF (ASTAGES * ASTAGE_BYTES)                 // 110592
#define ATTN_SMEM_BYTES (QST_OFF + 128*KV_PAD*2)         // 129024

__global__ __launch_bounds__(256, 1)
void attn_f16x2(const __half* __restrict__ qh, const __half* __restrict__ ql,
                const uint32_t* __restrict__ pm,
                __half* __restrict__ cth, __half* __restrict__ ctl)
{
    extern __shared__ __align__(16) char smem_raw[];
    __half* QstH = (__half*)(smem_raw + QST_OFF);

    const int tid  = threadIdx.x;
    const int warp = tid >> 5, lane = tid & 31;
    const int g = lane >> 2, t = lane & 3;
    const int b  = blockIdx.y >> 4;
    const int h  = blockIdx.y & 15;
    const int q0 = blockIdx.x * 128;

    const size_t rowbase = (size_t)b * LL;
    const uint32_t* pmb = pm + (size_t)b * LL * (LL/32);

    // ---- stage Q hi plane ---------------------------------------------------
    #pragma unroll
    for (int p = 0; p < 4; p++) {
        int idx = p * 256 + tid;            // 128 rows x 8 segs
        int r   = idx >> 3;
        int ch  = (idx & 7) * 8;
        cp_async16(&QstH[r*KV_PAD + ch],
                   qh + (rowbase + q0 + r) * (size_t)D3 + h*64 + ch);
    }
    CP_COMMIT();

    // ---- KV pipeline --------------------------------------------------------
    auto load_kv = [&](int tile, int slot) {
        char* sb = smem_raw + slot * ASTAGE_BYTES;
        __half* KsH = (__half*)sb;
        __half* KsL = (__half*)(sb + 9216);
        __half* VsH = (__half*)(sb + 18432);
        __half* VsL = (__half*)(sb + 27648);
        const int k0 = tile * 64;
        #pragma unroll
        for (int p = 0; p < 2; p++) {
            int idx = p * 256 + tid;        // 64 rows x 8 segs
            int r   = idx >> 3;
            int ch  = (idx & 7) * 8;
            size_t base = (rowbase + k0 + r) * (size_t)D3 + h*64 + ch;
            cp_async16(&KsH[r*KV_PAD + ch], qh + base + 1024);
            cp_async16(&KsL[r*KV_PAD + ch], ql + base + 1024);
            cp_async16(&VsH[r*KV_PAD + ch], qh + base + 2048);
            cp_async16(&VsL[r*KV_PAD + ch], ql + base + 2048);
        }
    };

    load_kv(0, 0); CP_COMMIT();
    load_kv(1, 1); CP_COMMIT();

    float oc[8][4];
    #pragma unroll
    for (int ni = 0; ni < 8; ni++)
        #pragma unroll
        for (int j = 0; j < 4; j++) oc[ni][j] = 0.f;
    float mi0 = -1e30f, mi1 = -1e30f, li0 = 0.f, li1 = 0.f;

    const float cs = 0.18033688011112042f;  // log2(e)/sqrt(64)
    const int r0g = q0 + warp*16 + g;
    const int NT  = LL / 64;

    const int k_key = ((lane & 16) ? 8 : 0) + (lane & 7);
    const int k_dim = (lane & 8) ? 8 : 0;
    const int v_row = lane;
    const int q_row = warp*16 + (lane & 15);
    const int q_col = (lane >> 4) << 3;

    for (int tt = 0; tt < NT; tt++) {
        const int k0 = tt * 64;
        if (tt < NT - 1) CP_WAIT1(); else CP_WAIT0();
        __syncthreads();

        if (tt + 2 < NT) { load_kv(tt + 2, (tt + 2) % ASTAGES); CP_COMMIT(); }

        char* sb = smem_raw + (tt % ASTAGES) * ASTAGE_BYTES;
        const __half* KsH = (const __half*)sb;
        const __half* KsL = (const __half*)(sb + 9216);
        const __half* VsH = (const __half*)(sb + 18432);
        const __half* VsL = (const __half*)(sb + 27648);

        // ---- S = Q @ K^T (2-pass: qH*kH + qH*kL) ----------------------------
        float sc[8][4];
        #pragma unroll
        for (int ni = 0; ni < 8; ni++)
            #pragma unroll
            for (int j = 0; j < 4; j++) sc[ni][j] = 0.f;

        #pragma unroll
        for (int kb = 0; kb < 4; kb++) {
            uint32_t aqH[4];
            ldsm_x4(aqH, su32(QstH + q_row*KV_PAD + kb*16 + q_col));
            #pragma unroll
            for (int njp = 0; njp < 4; njp++) {
                uint32_t kH[4], kL[4];
                ldsm_x4(kH, su32(KsH + (njp*16 + k_key)*KV_PAD + kb*16 + k_dim));
                ldsm_x4(kL, su32(KsL + (njp*16 + k_key)*KV_PAD + kb*16 + k_dim));
                mma_f16(sc[2*njp],   aqH, kH[0], kH[1]);
                mma_f16(sc[2*njp],   aqH, kL[0], kL[1]);
                mma_f16(sc[2*njp+1], aqH, kH[2], kH[3]);
                mma_f16(sc[2*njp+1], aqH, kL[2], kL[3]);
            }
        }

        // ---- packed mask + online softmax (log2 domain) ---------------------
        const uint32_t* pr0 = pmb + (size_t)r0g * 64 + (k0 >> 5);
        const uint32_t* pr1 = pmb + (size_t)(r0g + 8) * 64 + (k0 >> 5);
        uint64_t m0 = (uint64_t)pr0[0] | ((uint64_t)pr0[1] << 32);
        uint64_t m1 = (uint64_t)pr1[0] | ((uint64_t)pr1[1] << 32);

        float tm0 = -1e30f, tm1 = -1e30f;
        uint32_t keep[8];
        #pragma unroll
        for (int ni = 0; ni < 8; ni++) {
            const int bit = ni*8 + 2*t;
            uint32_t p0 = (uint32_t)(m0 >> bit) & 3u;
            uint32_t p1 = (uint32_t)(m1 >> bit) & 3u;
            keep[ni] = p0 | (p1 << 2);
            sc[ni][0] = (p0 & 1) ? sc[ni][0]*cs : 0.f;
            sc[ni][1] = (p0 & 2) ? sc[ni][1]*cs : 0.f;
            sc[ni][2] = (p1 & 1) ? sc[ni][2]*cs : 0.f;
            sc[ni][3] = (p1 & 2) ? sc[ni][3]*cs : 0.f;
            tm0 = fmaxf(tm0, fmaxf(sc[ni][0], sc[ni][1]));
            tm1 = fmaxf(tm1, fmaxf(sc[ni][2], sc[ni][3]));
        }
        tm0 = fmaxf(tm0, __shfl_xor_sync(0xffffffffu, tm0, 1));
        tm0 = fmaxf(tm0, __shfl_xor_sync(0xffffffffu, tm0, 2));
        tm1 = fmaxf(tm1, __shfl_xor_sync(0xffffffffu, tm1, 1));
        tm1 = fmaxf(tm1, __shfl_xor_sync(0xffffffffu, tm1, 2));

        const float mn0 = fmaxf(mi0, tm0);
        const float mn1 = fmaxf(mi1, tm1);
        const float s0  = fexp2(mi0 - mn0);
        const float s1  = fexp2(mi1 - mn1);
        mi0 = mn0; mi1 = mn1;

        float sum0 = 0.f, sum1 = 0.f;
        #pragma unroll
        for (int ni = 0; ni < 8; ni++) {
            float e0 = fexp2(sc[ni][0] - mn0);
            float e1 = fexp2(sc[ni][1] - mn0);
            float e2 = fexp2(sc[ni][2] - mn1);
            float e3 = fexp2(sc[ni][3] - mn1);
            sum0 += e0 + e1;
            sum1 += e2 + e3;
            sc[ni][0] = (keep[ni] & 1) ? e0 : 0.f;
            sc[ni][1] = (keep[ni] & 2) ? e1 : 0.f;
            sc[ni][2] = (keep[ni] & 4) ? e2 : 0.f;
            sc[ni][3] = (keep[ni] & 8) ? e3 : 0.f;
        }
        sum0 += __shfl_xor_sync(0xffffffffu, sum0, 1);
        sum0 += __shfl_xor_sync(0xffffffffu, sum0, 2);
        sum1 += __shfl_xor_sync(0xffffffffu, sum1, 1);
        sum1 += __shfl_xor_sync(0xffffffffu, sum1, 2);
        li0 = li0 * s0 + sum0;
        li1 = li1 * s1 + sum1;

        #pragma unroll
        for (int ni = 0; ni < 8; ni++) {
            oc[ni][0] *= s0; oc[ni][1] *= s0;
            oc[ni][2] *= s1; oc[ni][3] *= s1;
        }

        // ---- O += P @ V (2-pass: pH*vH + pH*vL; P unsplit) ------------------
        #pragma unroll
        for (int kb2 = 0; kb2 < 2; kb2++) {
            uint32_t apH[2][4];
            #pragma unroll
            for (int kk = 0; kk < 2; kk++) {
                const int kbi = kb2*2 + kk;
                apH[kk][0] = h2bits(__floats2half2_rn(sc[2*kbi][0],   sc[2*kbi][1]));
                apH[kk][1] = h2bits(__floats2half2_rn(sc[2*kbi][2],   sc[2*kbi][3]));
                apH[kk][2] = h2bits(__floats2half2_rn(sc[2*kbi+1][0], sc[2*kbi+1][1]));
                apH[kk][3] = h2bits(__floats2half2_rn(sc[2*kbi+1][2], sc[2*kbi+1][3]));
            }
            #pragma unroll
            for (int nj = 0; nj < 8; nj++) {
                uint32_t vH[4], vL[4];
                ldsm_x4_t(vH, su32(VsH + (kb2*32 + v_row)*KV_PAD + nj*8));
                ldsm_x4_t(vL, su32(VsL + (kb2*32 + v_row)*KV_PAD + nj*8));
                mma_f16(oc[nj], apH[0], vH[0], vH[1]);
                mma_f16(oc[nj], apH[0], vL[0], vL[1]);
                mma_f16(oc[nj], apH[1], vH[2], vH[3]);
                mma_f16(oc[nj], apH[1], vL[2], vL[3]);
            }
        }
    }

    // ---- epilogue: ctx fp16 hi/lo planes ------------------------------------
    const float inv0 = 1.0f / li0;
    const float inv1 = 1.0f / li1;
    #pragma unroll
    for (int ni = 0; ni < 8; ni++) {
        const int c = h*64 + ni*8 + 2*t;
        uint32_t hp, lp;
        split_pair_h(oc[ni][0]*inv0, oc[ni][1]*inv0, hp, lp);
        *(uint32_t*)&cth[(rowbase + r0g) * DD + c] = hp;
        *(uint32_t*)&ctl[(rowbase + r0g) * DD + c] = lp;
        split_pair_h(oc[ni][2]*inv1, oc[ni][3]*inv1, hp, lp);
        *(uint32_t*)&cth[(rowbase + r0g + 8) * DD + c] = hp;
        *(uint32_t*)&ctl[(rowbase + r0g + 8) * DD + c] = lp;
    }
}

// ---------------------------------------------------------------------------
extern "C" void kernel_launch(void* const* d_in, const int* in_sizes, int n_in,
                              void* d_out, int out_size)
{
    const float* inputs = (const float*)d_in[0];
    const int*   mask   = (const int*)  d_in[1];
    const float* W1     = (const float*)d_in[2];
    const float* b1     = (const float*)d_in[3];
    const float* W2     = (const float*)d_in[4];
    const float* b2     = (const float*)d_in[5];
    float* out = (float*)d_out;

    __half *xh, *xl, *w1h, *w1l, *w2h, *w2l, *qh, *ql, *ch, *cl;
    uint32_t* pmm;
    cudaGetSymbolAddress((void**)&xh,  g_xh);  cudaGetSymbolAddress((void**)&xl,  g_xl);
    cudaGetSymbolAddress((void**)&w1h, g_w1h); cudaGetSymbolAddress((void**)&w1l, g_w1l);
    cudaGetSymbolAddress((void**)&w2h, g_w2h); cudaGetSymbolAddress((void**)&w2l, g_w2l);
    cudaGetSymbolAddress((void**)&qh,  g_qh);  cudaGetSymbolAddress((void**)&ql,  g_ql);
    cudaGetSymbolAddress((void**)&ch,  g_ch);  cudaGetSymbolAddress((void**)&cl,  g_cl);
    cudaGetSymbolAddress((void**)&pmm, g_pm);

    cudaFuncSetAttribute(gemm_f16x3<true>,
                         cudaFuncAttributeMaxDynamicSharedMemorySize, GEMM_SMEM_BYTES);
    cudaFuncSetAttribute(gemm_f16x3<false>,
                         cudaFuncAttributeMaxDynamicSharedMemorySize, GEMM_SMEM_BYTES);
    cudaFuncSetAttribute(attn_f16x2,
                         cudaFuncAttributeMaxDynamicSharedMemorySize, ATTN_SMEM_BYTES);

    // 0) pre-passes: fp16 hi/lo splits + mask bit-pack
    {
        int nx = NROWS*DD/4, n1 = DD*D3/4, n2 = DD*DD/4;
        split_kernel<<<(nx+255)/256, 256>>>(inputs, xh, xl, nx);
        split_kernel<<<(n1+255)/256, 256>>>(W1, w1h, w1l, n1);
        split_kernel<<<(n2+255)/256, 256>>>(W2, w2h, w2l, n2);
        int nw = BB*LL*(LL/32);
        pack_mask_kernel<<<(nw+255)/256, 256>>>(mask, pmm, nw);
    }
    // 1) QKV projection -> qkv fp16 hi/lo planes
    {
        dim3 grid(D3/128, NROWS/128);
        gemm_f16x3<true><<<grid, 512, GEMM_SMEM_BYTES>>>(
            xh, xl, w1h, w1l, b1, nullptr, qh, ql, NROWS, D3, DD);
    }
    // 2) fused masked attention (2-pass) -> ctx fp16 hi/lo planes
    {
        dim3 grid(LL/128, BB*HH);
        attn_f16x2<<<grid, 256, ATTN_SMEM_BYTES>>>(qh, ql, pmm, ch, cl);
    }
    // 3) output projection -> fp32 out
    {
        dim3 grid(DD/128, NROWS/128);
        gemm_f16x3<false><<<grid, 512, GEMM_SMEM_BYTES>>>(
            ch, cl, w2h, w2l, b2, out, nullptr, nullptr, NROWS, DD, DD);
    }
}